// round 4
// baseline (speedup 1.0000x reference)
#include <cuda_runtime.h>
#include <cstdint>

#define N_NODES 100000
#define N_EDGES 1600000
#define D 128
#define SCAN_BLOCK 512
#define NB_SCAN ((N_NODES + SCAN_BLOCK - 1) / SCAN_BLOCK)   // 196

// GEMM tiling
#define BM 128                       // rows per block
#define WS_PAD 136                   // W smem row stride (floats), conflict-free B frags
#define XS_PAD 132                   // x smem row stride (floats), conflict-free A frags

// ---- device scratch (allocation-free rule: __device__ globals) ----
__device__ float g_support[(size_t)N_NODES * D];   // x @ W
__device__ int   g_count[N_NODES];                 // histogram of dst
__device__ int   g_offset[N_NODES + 1];            // CSR row offsets
__device__ int   g_cursor[N_NODES];                // scatter cursors
__device__ int   g_blocksum[NB_SCAN];              // scan partials
__device__ uint2 g_edges[N_EDGES];                 // {src, float_bits(w)} sorted by dst

static_assert(NB_SCAN <= 256, "scan2 single block assumption");

// ---------------------------------------------------------------------------
// CSR build step 1: histogram of edge_dst
// ---------------------------------------------------------------------------
__global__ void hist_kernel(const int* __restrict__ edst)
{
    int i = blockIdx.x * blockDim.x + threadIdx.x;
    int stride = gridDim.x * blockDim.x;
    for (; i < N_EDGES; i += stride)
        atomicAdd(&g_count[edst[i]], 1);
}

// ---------------------------------------------------------------------------
// CSR build step 2a: per-block exclusive scan
// ---------------------------------------------------------------------------
__global__ void scan1_kernel()
{
    __shared__ int warp_sums[SCAN_BLOCK / 32];
    int tid = threadIdx.x;
    int gid = blockIdx.x * SCAN_BLOCK + tid;
    int v = (gid < N_NODES) ? g_count[gid] : 0;

    int x = v;
    #pragma unroll
    for (int o = 1; o < 32; o <<= 1) {
        int y = __shfl_up_sync(0xFFFFFFFFu, x, o);
        if ((tid & 31) >= o) x += y;
    }
    if ((tid & 31) == 31) warp_sums[tid >> 5] = x;
    __syncthreads();
    if (tid < 32) {
        const int nw = SCAN_BLOCK / 32;
        int s = (tid < nw) ? warp_sums[tid] : 0;
        #pragma unroll
        for (int o = 1; o < 32; o <<= 1) {
            int y = __shfl_up_sync(0xFFFFFFFFu, s, o);
            if (tid >= o) s += y;
        }
        if (tid < nw) warp_sums[tid] = s;
    }
    __syncthreads();
    int base = (tid >= 32) ? warp_sums[(tid >> 5) - 1] : 0;
    int incl = x + base;
    if (gid < N_NODES) g_offset[gid] = incl - v;
    if (tid == SCAN_BLOCK - 1) g_blocksum[blockIdx.x] = incl;
}

// ---------------------------------------------------------------------------
// CSR build step 2b: exclusive scan of block totals (1 block)
// ---------------------------------------------------------------------------
__global__ void scan2_kernel()
{
    __shared__ int sh[256];
    int tid = threadIdx.x;
    int v = (tid < NB_SCAN) ? g_blocksum[tid] : 0;
    sh[tid] = v;
    __syncthreads();
    #pragma unroll
    for (int o = 1; o < 256; o <<= 1) {
        int y = (tid >= o) ? sh[tid - o] : 0;
        __syncthreads();
        sh[tid] += y;
        __syncthreads();
    }
    if (tid < NB_SCAN) g_blocksum[tid] = sh[tid] - v;
}

// ---------------------------------------------------------------------------
// CSR build step 2c: add block bases, init cursors, cap offsets
// ---------------------------------------------------------------------------
__global__ void scan3_kernel()
{
    int gid = blockIdx.x * SCAN_BLOCK + threadIdx.x;
    if (gid < N_NODES) {
        int o = g_offset[gid] + g_blocksum[blockIdx.x];
        g_offset[gid] = o;
        g_cursor[gid] = o;
    }
    if (gid == 0) g_offset[N_NODES] = N_EDGES;
}

// ---------------------------------------------------------------------------
// CSR build step 3: scatter edges into dst-sorted order
// ---------------------------------------------------------------------------
__global__ void scatter_kernel(const int* __restrict__ esrc,
                               const int* __restrict__ edst,
                               const float* __restrict__ ew)
{
    int i = blockIdx.x * blockDim.x + threadIdx.x;
    int stride = gridDim.x * blockDim.x;
    for (; i < N_EDGES; i += stride) {
        int d = edst[i];
        int pos = atomicAdd(&g_cursor[d], 1);
        g_edges[pos] = make_uint2((unsigned)esrc[i], __float_as_uint(ew[i]));
    }
}

// ---------------------------------------------------------------------------
// 3xTF32 tensor-core GEMM: support = x @ W
// Block: 256 threads (8 warps x m16), tile BM=128 rows x 128 cols.
// mma.sync m16n8k8 tf32 with hi/lo error compensation (fp32-grade accuracy).
// ---------------------------------------------------------------------------
__device__ __forceinline__ void split_tf32(float v, uint32_t& hi, uint32_t& lo)
{
    uint32_t h;
    asm("cvt.rna.tf32.f32 %0, %1;" : "=r"(h) : "f"(v));
    float r = v - __uint_as_float(h);
    uint32_t l;
    asm("cvt.rna.tf32.f32 %0, %1;" : "=r"(l) : "f"(r));
    hi = h; lo = l;
}

__device__ __forceinline__ void mma_tf32(float* c, const uint32_t* a, uint32_t b0, uint32_t b1)
{
    asm volatile(
        "mma.sync.aligned.m16n8k8.row.col.f32.tf32.tf32.f32 "
        "{%0,%1,%2,%3}, {%4,%5,%6,%7}, {%8,%9}, {%0,%1,%2,%3};"
        : "+f"(c[0]), "+f"(c[1]), "+f"(c[2]), "+f"(c[3])
        : "r"(a[0]), "r"(a[1]), "r"(a[2]), "r"(a[3]), "r"(b0), "r"(b1));
}

__global__ void gemm_tc_kernel(const float* __restrict__ x,
                               const float* __restrict__ W,
                               float* __restrict__ support)
{
    extern __shared__ float smem[];
    float* Ws = smem;                       // [128][WS_PAD]
    float* xs = smem + 128 * WS_PAD;        // [BM][XS_PAD]

    int tid  = threadIdx.x;
    int warp = tid >> 5;
    int lane = tid & 31;
    int m0   = blockIdx.x * BM;

    // Load W (4096 float4). Ws padded: float4 row stride = WS_PAD/4 = 34.
    {
        const float4* Wg = (const float4*)W;
        float4* Ws4 = (float4*)Ws;
        #pragma unroll
        for (int i = 0; i < 16; i++) {
            int idx = tid + i * 256;
            int row = idx >> 5;
            int c4  = idx & 31;
            Ws4[row * (WS_PAD / 4) + c4] = Wg[idx];
        }
    }
    // Load x tile (4096 float4), zero-padded past N_NODES. xs float4 stride 33.
    {
        const float4* xg = (const float4*)x;
        float4* xs4 = (float4*)xs;
        #pragma unroll
        for (int i = 0; i < 16; i++) {
            int idx = tid + i * 256;
            int r  = idx >> 5;
            int c4 = idx & 31;
            int row = m0 + r;
            float4 v = make_float4(0.f, 0.f, 0.f, 0.f);
            if (row < N_NODES) v = xg[(size_t)row * 32 + c4];
            xs4[r * (XS_PAD / 4) + c4] = v;
        }
    }
    __syncthreads();

    int qr = lane >> 2;    // 0..7
    int qc = lane & 3;     // 0..3
    int mrow = warp * 16;

    float acc[16][4];
    #pragma unroll
    for (int nt = 0; nt < 16; nt++)
        #pragma unroll
        for (int c = 0; c < 4; c++) acc[nt][c] = 0.f;

    #pragma unroll 1
    for (int kk = 0; kk < 16; kk++) {
        int k0 = kk * 8;
        // A fragment (m16k8) + tf32 hi/lo split
        float av[4];
        av[0] = xs[(mrow + qr)     * XS_PAD + k0 + qc];
        av[1] = xs[(mrow + qr + 8) * XS_PAD + k0 + qc];
        av[2] = xs[(mrow + qr)     * XS_PAD + k0 + qc + 4];
        av[3] = xs[(mrow + qr + 8) * XS_PAD + k0 + qc + 4];
        uint32_t ah[4], al[4];
        #pragma unroll
        for (int i = 0; i < 4; i++) split_tf32(av[i], ah[i], al[i]);

        #pragma unroll
        for (int nt = 0; nt < 16; nt++) {
            int n0 = nt * 8;
            float bv0 = Ws[(k0 + qc)     * WS_PAD + n0 + qr];
            float bv1 = Ws[(k0 + 4 + qc) * WS_PAD + n0 + qr];
            uint32_t bh0, bl0, bh1, bl1;
            split_tf32(bv0, bh0, bl0);
            split_tf32(bv1, bh1, bl1);
            mma_tf32(acc[nt], ah, bh0, bh1);   // hi*hi
            mma_tf32(acc[nt], ah, bl0, bl1);   // hi*lo
            mma_tf32(acc[nt], al, bh0, bh1);   // lo*hi
        }
    }

    // Store: c0/c1 -> (row0, col..col+1), c2/c3 -> (row0+8, col..col+1)
    int row0 = m0 + mrow + qr;
    int row1 = row0 + 8;
    #pragma unroll
    for (int nt = 0; nt < 16; nt++) {
        int col = nt * 8 + 2 * qc;
        if (row0 < N_NODES)
            *(float2*)&support[(size_t)row0 * D + col] = make_float2(acc[nt][0], acc[nt][1]);
        if (row1 < N_NODES)
            *(float2*)&support[(size_t)row1 * D + col] = make_float2(acc[nt][2], acc[nt][3]);
    }
}

// ---------------------------------------------------------------------------
// Gather SpMM: one warp per dst node. out[d] = bias + sum w_e * support[src_e]
// ---------------------------------------------------------------------------
__global__ void gather_kernel(const float* __restrict__ bias,
                              float* __restrict__ out)
{
    int warp = (blockIdx.x * blockDim.x + threadIdx.x) >> 5;
    int lane = threadIdx.x & 31;
    if (warp >= N_NODES) return;

    int start = g_offset[warp];
    int end   = g_offset[warp + 1];

    const float4* sup4 = (const float4*)g_support;
    float4 acc = __ldg(&((const float4*)bias)[lane]);

    for (int i = start; i < end; i += 32) {
        int n = end - i;
        if (n > 32) n = 32;
        uint2 em = make_uint2(0u, 0u);
        if (lane < n) em = g_edges[i + lane];
        for (int j = 0; j < n; j++) {
            unsigned s = __shfl_sync(0xFFFFFFFFu, em.x, j);
            float    w = __uint_as_float(__shfl_sync(0xFFFFFFFFu, em.y, j));
            float4 v = sup4[(size_t)s * (D / 4) + lane];
            acc.x += w * v.x;
            acc.y += w * v.y;
            acc.z += w * v.z;
            acc.w += w * v.w;
        }
    }
    ((float4*)out)[(size_t)warp * (D / 4) + lane] = acc;
}

// ---------------------------------------------------------------------------
// Launch.  Inputs: x, edge_src, edge_dst, edge_weight, W, bias. Output fp32.
// ---------------------------------------------------------------------------
extern "C" void kernel_launch(void* const* d_in, const int* in_sizes, int n_in,
                              void* d_out, int out_size)
{
    const float* x    = (const float*)d_in[0];
    const int*   esrc = (const int*)d_in[1];
    const int*   edst = (const int*)d_in[2];
    const float* ew   = (const float*)d_in[3];
    const float* W    = (const float*)d_in[4];
    const float* bias = (const float*)d_in[5];
    float* out = (float*)d_out;

    float* support;
    cudaGetSymbolAddress((void**)&support, g_support);
    void* countPtr;
    cudaGetSymbolAddress(&countPtr, g_count);

    // --- CSR build ---
    cudaMemsetAsync(countPtr, 0, N_NODES * sizeof(int));
    hist_kernel<<<1024, 256>>>(edst);
    scan1_kernel<<<NB_SCAN, SCAN_BLOCK>>>();
    scan2_kernel<<<1, 256>>>();
    scan3_kernel<<<NB_SCAN, SCAN_BLOCK>>>();
    scatter_kernel<<<1024, 256>>>(esrc, edst, ew);

    // --- dense projection (3xTF32 tensor-core GEMM) ---
    {
        static const int smem_bytes = (128 * WS_PAD + BM * XS_PAD) * (int)sizeof(float); // ~137 KB
        cudaFuncSetAttribute(gemm_tc_kernel, cudaFuncAttributeMaxDynamicSharedMemorySize, smem_bytes);
        int blocks = (N_NODES + BM - 1) / BM;
        gemm_tc_kernel<<<blocks, 256, smem_bytes>>>(x, W, support);
    }

    // --- gather SpMM + bias ---
    {
        int warps_per_block = 8;
        int blocks = (N_NODES + warps_per_block - 1) / warps_per_block;
        gather_kernel<<<blocks, 256>>>(bias, out);
    }
}

// round 6
// speedup vs baseline: 1.1540x; 1.1540x over previous
#include <cuda_runtime.h>
#include <cstdint>

#define N_NODES 100000
#define N_EDGES 1600000
#define D 128
#define SCAN_BLOCK 512
#define NB_SCAN ((N_NODES + SCAN_BLOCK - 1) / SCAN_BLOCK)   // 196

// GEMM tiling
#define BM 128                        // rows per block
#define WS_PAD 136                    // W smem row stride (words): conflict-free B frags
#define XS_PAD 132                    // x smem row stride (words): conflict-free A frags

// ---- device scratch (allocation-free rule: __device__ globals) ----
__device__ float g_support[(size_t)N_NODES * D];   // x @ W
__device__ int   g_count[N_NODES];                 // histogram of dst
__device__ int   g_offset[N_NODES + 1];            // CSR row offsets
__device__ int   g_cursor[N_NODES];                // scatter cursors
__device__ int   g_blocksum[NB_SCAN];              // scan partials
__device__ uint2 g_edges[N_EDGES];                 // {src, float_bits(w)} sorted by dst

static_assert(NB_SCAN <= 256, "scan2 single block assumption");

// ---------------------------------------------------------------------------
// CSR build step 1: histogram of edge_dst
// ---------------------------------------------------------------------------
__global__ void hist_kernel(const int* __restrict__ edst)
{
    int i = blockIdx.x * blockDim.x + threadIdx.x;
    int stride = gridDim.x * blockDim.x;
    for (; i < N_EDGES; i += stride)
        atomicAdd(&g_count[edst[i]], 1);
}

// ---------------------------------------------------------------------------
// CSR build step 2a: per-block exclusive scan
// ---------------------------------------------------------------------------
__global__ void scan1_kernel()
{
    __shared__ int warp_sums[SCAN_BLOCK / 32];
    int tid = threadIdx.x;
    int gid = blockIdx.x * SCAN_BLOCK + tid;
    int v = (gid < N_NODES) ? g_count[gid] : 0;

    int x = v;
    #pragma unroll
    for (int o = 1; o < 32; o <<= 1) {
        int y = __shfl_up_sync(0xFFFFFFFFu, x, o);
        if ((tid & 31) >= o) x += y;
    }
    if ((tid & 31) == 31) warp_sums[tid >> 5] = x;
    __syncthreads();
    if (tid < 32) {
        const int nw = SCAN_BLOCK / 32;
        int s = (tid < nw) ? warp_sums[tid] : 0;
        #pragma unroll
        for (int o = 1; o < 32; o <<= 1) {
            int y = __shfl_up_sync(0xFFFFFFFFu, s, o);
            if (tid >= o) s += y;
        }
        if (tid < nw) warp_sums[tid] = s;
    }
    __syncthreads();
    int base = (tid >= 32) ? warp_sums[(tid >> 5) - 1] : 0;
    int incl = x + base;
    if (gid < N_NODES) g_offset[gid] = incl - v;
    if (tid == SCAN_BLOCK - 1) g_blocksum[blockIdx.x] = incl;
}

// ---------------------------------------------------------------------------
// CSR build step 2b: exclusive scan of block totals (1 block)
// ---------------------------------------------------------------------------
__global__ void scan2_kernel()
{
    __shared__ int sh[256];
    int tid = threadIdx.x;
    int v = (tid < NB_SCAN) ? g_blocksum[tid] : 0;
    sh[tid] = v;
    __syncthreads();
    #pragma unroll
    for (int o = 1; o < 256; o <<= 1) {
        int y = (tid >= o) ? sh[tid - o] : 0;
        __syncthreads();
        sh[tid] += y;
        __syncthreads();
    }
    if (tid < NB_SCAN) g_blocksum[tid] = sh[tid] - v;
}

// ---------------------------------------------------------------------------
// CSR build step 2c: add block bases, init cursors, cap offsets
// ---------------------------------------------------------------------------
__global__ void scan3_kernel()
{
    int gid = blockIdx.x * SCAN_BLOCK + threadIdx.x;
    if (gid < N_NODES) {
        int o = g_offset[gid] + g_blocksum[blockIdx.x];
        g_offset[gid] = o;
        g_cursor[gid] = o;
    }
    if (gid == 0) g_offset[N_NODES] = N_EDGES;
}

// ---------------------------------------------------------------------------
// CSR build step 3: scatter edges into dst-sorted order
// ---------------------------------------------------------------------------
__global__ void scatter_kernel(const int* __restrict__ esrc,
                               const int* __restrict__ edst,
                               const float* __restrict__ ew)
{
    int i = blockIdx.x * blockDim.x + threadIdx.x;
    int stride = gridDim.x * blockDim.x;
    for (; i < N_EDGES; i += stride) {
        int d = edst[i];
        int pos = atomicAdd(&g_cursor[d], 1);
        g_edges[pos] = make_uint2((unsigned)esrc[i], __float_as_uint(ew[i]));
    }
}

// ---------------------------------------------------------------------------
// 3xTF32 tensor-core GEMM, v2: W pre-split into Whi/Wlo in smem at load time;
// A split on the fly (A-frag reused across all 16 n-tiles). Inner loop is
// pure LDS + MMA.
// ---------------------------------------------------------------------------
__device__ __forceinline__ void split_tf32(float v, uint32_t& hi, uint32_t& lo)
{
    uint32_t h;
    asm("cvt.rna.tf32.f32 %0, %1;" : "=r"(h) : "f"(v));
    float r = v - __uint_as_float(h);
    uint32_t l;
    asm("cvt.rna.tf32.f32 %0, %1;" : "=r"(l) : "f"(r));
    hi = h; lo = l;
}

__device__ __forceinline__ void mma_tf32(float* c, const uint32_t* a, uint32_t b0, uint32_t b1)
{
    asm volatile(
        "mma.sync.aligned.m16n8k8.row.col.f32.tf32.tf32.f32 "
        "{%0,%1,%2,%3}, {%4,%5,%6,%7}, {%8,%9}, {%0,%1,%2,%3};"
        : "+f"(c[0]), "+f"(c[1]), "+f"(c[2]), "+f"(c[3])
        : "r"(a[0]), "r"(a[1]), "r"(a[2]), "r"(a[3]), "r"(b0), "r"(b1));
}

__global__ void gemm_tc_kernel(const float* __restrict__ x,
                               const float* __restrict__ W,
                               float* __restrict__ support)
{
    extern __shared__ float smem[];
    uint32_t* Whi = (uint32_t*)smem;                    // [128][WS_PAD]
    uint32_t* Wlo = Whi + 128 * WS_PAD;                 // [128][WS_PAD]
    float*    xs  = (float*)(Wlo + 128 * WS_PAD);      // [BM][XS_PAD]

    int tid  = threadIdx.x;
    int warp = tid >> 5;
    int lane = tid & 31;
    int m0   = blockIdx.x * BM;

    // Load + split W (4096 float4 -> Whi/Wlo uint4, padded stride 34 uint4).
    {
        const float4* Wg = (const float4*)W;
        uint4* Whi4 = (uint4*)Whi;
        uint4* Wlo4 = (uint4*)Wlo;
        #pragma unroll
        for (int i = 0; i < 16; i++) {
            int idx = tid + i * 256;
            int row = idx >> 5;
            int c4  = idx & 31;
            float4 v = Wg[idx];
            uint4 h, l;
            split_tf32(v.x, h.x, l.x);
            split_tf32(v.y, h.y, l.y);
            split_tf32(v.z, h.z, l.z);
            split_tf32(v.w, h.w, l.w);
            int o = row * (WS_PAD / 4) + c4;
            Whi4[o] = h;
            Wlo4[o] = l;
        }
    }
    // Load x tile (fp32, zero-padded past N_NODES), float4 stride 33.
    {
        const float4* xg = (const float4*)x;
        float4* xs4 = (float4*)xs;
        #pragma unroll
        for (int i = 0; i < 16; i++) {
            int idx = tid + i * 256;
            int r  = idx >> 5;
            int c4 = idx & 31;
            int row = m0 + r;
            float4 v = make_float4(0.f, 0.f, 0.f, 0.f);
            if (row < N_NODES) v = xg[(size_t)row * 32 + c4];
            xs4[r * (XS_PAD / 4) + c4] = v;
        }
    }
    __syncthreads();

    int qr = lane >> 2;    // 0..7
    int qc = lane & 3;     // 0..3
    int mrow = warp * 16;

    float acc[16][4];
    #pragma unroll
    for (int nt = 0; nt < 16; nt++)
        #pragma unroll
        for (int c = 0; c < 4; c++) acc[nt][c] = 0.f;

    #pragma unroll 1
    for (int kk = 0; kk < 16; kk++) {
        int k0 = kk * 8;
        // A fragment (m16k8) + split (reused across all 16 n-tiles)
        float av[4];
        av[0] = xs[(mrow + qr)     * XS_PAD + k0 + qc];
        av[1] = xs[(mrow + qr + 8) * XS_PAD + k0 + qc];
        av[2] = xs[(mrow + qr)     * XS_PAD + k0 + qc + 4];
        av[3] = xs[(mrow + qr + 8) * XS_PAD + k0 + qc + 4];
        uint32_t ah[4], al[4];
        #pragma unroll
        for (int i = 0; i < 4; i++) split_tf32(av[i], ah[i], al[i]);

        int rb0 = (k0 + qc) * WS_PAD + qr;       // b0 row base
        int rb1 = rb0 + 4 * WS_PAD;              // b1 row base (k+4)
        #pragma unroll
        for (int nt = 0; nt < 16; nt++) {
            int n0 = nt * 8;
            uint32_t bh0 = Whi[rb0 + n0];
            uint32_t bh1 = Whi[rb1 + n0];
            uint32_t bl0 = Wlo[rb0 + n0];
            uint32_t bl1 = Wlo[rb1 + n0];
            mma_tf32(acc[nt], ah, bh0, bh1);   // hi*hi
            mma_tf32(acc[nt], ah, bl0, bl1);   // hi*lo
            mma_tf32(acc[nt], al, bh0, bh1);   // lo*hi
        }
    }

    int row0 = m0 + mrow + qr;
    int row1 = row0 + 8;
    #pragma unroll
    for (int nt = 0; nt < 16; nt++) {
        int col = nt * 8 + 2 * qc;
        if (row0 < N_NODES)
            *(float2*)&support[(size_t)row0 * D + col] = make_float2(acc[nt][0], acc[nt][1]);
        if (row1 < N_NODES)
            *(float2*)&support[(size_t)row1 * D + col] = make_float2(acc[nt][2], acc[nt][3]);
    }
}

// ---------------------------------------------------------------------------
// Gather SpMM: one warp per dst node. out[d] = bias + sum w_e * support[src_e]
// ---------------------------------------------------------------------------
__global__ void gather_kernel(const float* __restrict__ bias,
                              float* __restrict__ out)
{
    int warp = (blockIdx.x * blockDim.x + threadIdx.x) >> 5;
    int lane = threadIdx.x & 31;
    if (warp >= N_NODES) return;

    int start = g_offset[warp];
    int end   = g_offset[warp + 1];

    const float4* sup4 = (const float4*)g_support;
    float4 acc = __ldg(&((const float4*)bias)[lane]);

    for (int i = start; i < end; i += 32) {
        int n = end - i;
        if (n > 32) n = 32;
        uint2 em = make_uint2(0u, 0u);
        if (lane < n) em = g_edges[i + lane];
        for (int j = 0; j < n; j++) {
            unsigned s = __shfl_sync(0xFFFFFFFFu, em.x, j);
            float    w = __uint_as_float(__shfl_sync(0xFFFFFFFFu, em.y, j));
            float4 v = sup4[(size_t)s * (D / 4) + lane];
            acc.x += w * v.x;
            acc.y += w * v.y;
            acc.z += w * v.z;
            acc.w += w * v.w;
        }
    }
    ((float4*)out)[(size_t)warp * (D / 4) + lane] = acc;
}

// ---------------------------------------------------------------------------
// Launch with fork/join: CSR build (side stream) overlaps GEMM (main stream);
// both join before gather. kernel_launch is only called a handful of times
// (correctness + capture), so per-call stream/event creation is fine and we
// deliberately do not destroy them while capture may still reference them.
// ---------------------------------------------------------------------------
extern "C" void kernel_launch(void* const* d_in, const int* in_sizes, int n_in,
                              void* d_out, int out_size)
{
    const float* x    = (const float*)d_in[0];
    const int*   esrc = (const int*)d_in[1];
    const int*   edst = (const int*)d_in[2];
    const float* ew   = (const float*)d_in[3];
    const float* W    = (const float*)d_in[4];
    const float* bias = (const float*)d_in[5];
    float* out = (float*)d_out;

    void* countPtr;
    cudaGetSymbolAddress(&countPtr, g_count);

    // Stream 0 is the capture stream (harness launches us on the default/capture
    // stream; legacy default stream semantics make these launches captured).
    cudaStream_t main_s = 0;
    cudaStream_t side_s;
    cudaStreamCreateWithFlags(&side_s, cudaStreamNonBlocking);
    cudaEvent_t ev_fork, ev_join;
    cudaEventCreateWithFlags(&ev_fork, cudaEventDisableTiming);
    cudaEventCreateWithFlags(&ev_join, cudaEventDisableTiming);

    // ---- fork ----
    cudaEventRecord(ev_fork, main_s);
    cudaStreamWaitEvent(side_s, ev_fork, 0);

    // side stream: CSR build chain
    cudaMemsetAsync(countPtr, 0, N_NODES * sizeof(int), side_s);
    hist_kernel<<<1024, 256, 0, side_s>>>(edst);
    scan1_kernel<<<NB_SCAN, SCAN_BLOCK, 0, side_s>>>();
    scan2_kernel<<<1, 256, 0, side_s>>>();
    scan3_kernel<<<NB_SCAN, SCAN_BLOCK, 0, side_s>>>();
    scatter_kernel<<<1024, 256, 0, side_s>>>(esrc, edst, ew);
    cudaEventRecord(ev_join, side_s);

    // main stream: dense projection (3xTF32 tensor-core GEMM)
    {
        float* support;
        cudaGetSymbolAddress((void**)&support, g_support);
        static const int smem_bytes =
            (2 * 128 * WS_PAD + BM * XS_PAD) * (int)sizeof(float);  // ~202 KB
        cudaFuncSetAttribute(gemm_tc_kernel,
                             cudaFuncAttributeMaxDynamicSharedMemorySize, smem_bytes);
        int blocks = (N_NODES + BM - 1) / BM;
        gemm_tc_kernel<<<blocks, 256, smem_bytes, main_s>>>(x, W, support);
    }

    // ---- join ----
    cudaStreamWaitEvent(main_s, ev_join, 0);

    // gather SpMM + bias
    {
        int warps_per_block = 8;
        int blocks = (N_NODES + warps_per_block - 1) / warps_per_block;
        gather_kernel<<<blocks, 256, 0, main_s>>>(bias, out);
    }
}